// round 1
// baseline (speedup 1.0000x reference)
#include <cuda_runtime.h>

#define B    64
#define HID  768
#define VSZ  30000
#define TLEN 32
#define C1   512

__device__ float g_h[2][B * HID];
__device__ float g_c[B * HID];
__device__ float g_hidden[B * C1];
__device__ unsigned long long g_amax[2][B];

__device__ __forceinline__ unsigned int ford(float f) {
    unsigned int u = __float_as_uint(f);
    return u ^ (((int)u >> 31) | 0x80000000u);
}
__device__ __forceinline__ float sigm(float x) { return 1.0f / (1.0f + expf(-x)); }

// ---------------------------------------------------------------------------
// init: h0 = feat, c0 = 0, reset argmax slots
// ---------------------------------------------------------------------------
__global__ void init_kernel(const float* __restrict__ fused) {
    int i = blockIdx.x * blockDim.x + threadIdx.x;
    if (i < B * HID) {
        g_h[0][i] = fused[i];
        g_c[i] = 0.0f;
    }
    if (blockIdx.x == 0 && threadIdx.x < B) {
        g_amax[0][threadIdx.x] = 0ull;
        g_amax[1][threadIdx.x] = 0ull;
    }
}

// ---------------------------------------------------------------------------
// closed path: relu(feat @ c1_W^T + c1_b) @ c2_W^T + c2_b
// ---------------------------------------------------------------------------
__global__ void closed1_kernel(const float* __restrict__ fused,
                               const float* __restrict__ c1_W,
                               const float* __restrict__ c1_b) {
    __shared__ float w[HID];
    int j = blockIdx.x;  // hidden column 0..511
    for (int k = threadIdx.x; k < HID; k += 64) w[k] = c1_W[j * HID + k];
    __syncthreads();
    int b = threadIdx.x;  // 64 threads = batch
    float acc = 0.0f;
    for (int k = 0; k < HID; ++k) acc += fused[b * HID + k] * w[k];
    acc += c1_b[j];
    g_hidden[b * C1 + j] = fmaxf(acc, 0.0f);
}

__global__ void closed2_kernel(const float* __restrict__ c2_W,
                               const float* __restrict__ c2_b,
                               float* __restrict__ out) {
    int tid = threadIdx.x;  // 128 threads
    int b = tid >> 1, cls = tid & 1;
    float acc = 0.0f;
    for (int k = 0; k < C1; ++k) acc += g_hidden[b * C1 + k] * c2_W[cls * C1 + k];
    out[b * 2 + cls] = acc + c2_b[cls];
}

// ---------------------------------------------------------------------------
// gates: gates = emb[tok] @ W_ih^T + h @ W_hh^T + b_ih + b_hh, LSTM cell update
// Also: extract tok from previous step's argmax, write generated[:, t-1],
// reset argmax slot for this step's logits pass.
// Block covers 4 hidden units (16 gate columns), all 64 batches. Grid = 192.
// ---------------------------------------------------------------------------
__global__ void gates_kernel(const float* __restrict__ emb,
                             const float* __restrict__ W_ih,
                             const float* __restrict__ W_hh,
                             const float* __restrict__ b_ih,
                             const float* __restrict__ b_hh,
                             int t, float* __restrict__ out) {
    __shared__ float As[16][B];    // [k][m]
    __shared__ float Bs[16][16];   // [k][n]
    __shared__ float gsm[B * 16];
    __shared__ int tok_s[B];

    const int tid = threadIdx.x;   // 128 threads
    const int U0 = blockIdx.x * 4;
    const float* __restrict__ h_read = g_h[t & 1];
    float* __restrict__ h_write = g_h[(t + 1) & 1];

    if (tid < B) {
        int tok = 0;
        if (t > 0) tok = (int)(~(unsigned int)(g_amax[(t - 1) & 1][tid]));
        tok_s[tid] = tok;
        g_amax[t & 1][tid] = 0ull;  // reset slot for this step's logits
        if (t > 0 && blockIdx.x == 0)
            out[2 * B + tid * TLEN + (t - 1)] = (float)tok;
    }
    __syncthreads();

    const int tx = tid & 7;    // cols tx*2 .. +1
    const int ty = tid >> 3;   // rows ty*4 .. +3
    float acc[4][2] = {};

    for (int k0 = 0; k0 < 2 * HID; k0 += 16) {
        // A tile: 64 rows x 16 k = 256 float4, 2 per thread
#pragma unroll
        for (int j = 0; j < 2; ++j) {
            int idx = tid * 2 + j;
            int m = idx >> 2, q = idx & 3;
            const float* src;
            if (k0 < HID) src = emb + (size_t)tok_s[m] * HID + k0 + q * 4;
            else          src = h_read + m * HID + (k0 - HID) + q * 4;
            float4 v = *(const float4*)src;
            As[q * 4 + 0][m] = v.x; As[q * 4 + 1][m] = v.y;
            As[q * 4 + 2][m] = v.z; As[q * 4 + 3][m] = v.w;
        }
        // B tile: 16 cols x 16 k = 64 float4
        if (tid < 64) {
            int n = tid >> 2, q = tid & 3;
            int gg = n >> 2, uu = n & 3;
            int row = gg * HID + U0 + uu;
            const float* src = (k0 < HID)
                ? (W_ih + (size_t)row * HID + k0 + q * 4)
                : (W_hh + (size_t)row * HID + (k0 - HID) + q * 4);
            float4 v = *(const float4*)src;
            Bs[q * 4 + 0][n] = v.x; Bs[q * 4 + 1][n] = v.y;
            Bs[q * 4 + 2][n] = v.z; Bs[q * 4 + 3][n] = v.w;
        }
        __syncthreads();
#pragma unroll
        for (int kk = 0; kk < 16; ++kk) {
            float a[4];
            *(float4*)&a[0] = *(const float4*)&As[kk][ty * 4];
            float b0 = Bs[kk][tx * 2 + 0];
            float b1 = Bs[kk][tx * 2 + 1];
#pragma unroll
            for (int i = 0; i < 4; ++i) {
                acc[i][0] += a[i] * b0;
                acc[i][1] += a[i] * b1;
            }
        }
        __syncthreads();
    }

#pragma unroll
    for (int i = 0; i < 4; ++i)
#pragma unroll
        for (int j = 0; j < 2; ++j)
            gsm[(ty * 4 + i) * 16 + tx * 2 + j] = acc[i][j];
    __syncthreads();

    for (int idx = tid; idx < 256; idx += 128) {
        int b = idx >> 2, uu = idx & 3, u = U0 + uu;
        float ig = gsm[b * 16 + 0 + uu]  + b_ih[u]           + b_hh[u];
        float fg = gsm[b * 16 + 4 + uu]  + b_ih[HID + u]     + b_hh[HID + u];
        float gg = gsm[b * 16 + 8 + uu]  + b_ih[2 * HID + u] + b_hh[2 * HID + u];
        float og = gsm[b * 16 + 12 + uu] + b_ih[3 * HID + u] + b_hh[3 * HID + u];
        float cn = sigm(fg) * g_c[b * HID + u] + sigm(ig) * tanhf(gg);
        g_c[b * HID + u] = cn;
        h_write[b * HID + u] = sigm(og) * tanhf(cn);
    }
}

// ---------------------------------------------------------------------------
// logits + argmax: 64x64 block tile, K=768, per-block reduction then one
// packed-u64 atomicMax per (block, batch). Grid = ceil(30000/64) = 469.
// ---------------------------------------------------------------------------
__global__ void logits_kernel(const float* __restrict__ out_W,
                              const float* __restrict__ out_b,
                              int t) {
    __shared__ float As[16][B];    // [k][m]
    __shared__ float Bs[16][64];   // [k][n]
    const float* __restrict__ h_read = g_h[(t + 1) & 1];

    const int tid = threadIdx.x;   // 128 threads
    const int tx = tid & 15;       // cols tx*4 .. +3
    const int ty = tid >> 4;       // rows ty*8 .. +7
    const int v0 = blockIdx.x * 64;

    float acc[8][4] = {};

    for (int k0 = 0; k0 < HID; k0 += 16) {
#pragma unroll
        for (int j = 0; j < 2; ++j) {
            int idx = tid * 2 + j;
            int m = idx >> 2, q = idx & 3;
            float4 v = *(const float4*)(h_read + m * HID + k0 + q * 4);
            As[q * 4 + 0][m] = v.x; As[q * 4 + 1][m] = v.y;
            As[q * 4 + 2][m] = v.z; As[q * 4 + 3][m] = v.w;
        }
#pragma unroll
        for (int j = 0; j < 2; ++j) {
            int idx = tid * 2 + j;
            int n = idx >> 2, q = idx & 3;
            int v = v0 + n;
            float4 w = make_float4(0.f, 0.f, 0.f, 0.f);
            if (v < VSZ) w = *(const float4*)(out_W + (size_t)v * HID + k0 + q * 4);
            Bs[q * 4 + 0][n] = w.x; Bs[q * 4 + 1][n] = w.y;
            Bs[q * 4 + 2][n] = w.z; Bs[q * 4 + 3][n] = w.w;
        }
        __syncthreads();
#pragma unroll
        for (int kk = 0; kk < 16; ++kk) {
            float a[8];
            *(float4*)&a[0] = *(const float4*)&As[kk][ty * 8];
            *(float4*)&a[4] = *(const float4*)&As[kk][ty * 8 + 4];
            float bv[4];
            *(float4*)&bv[0] = *(const float4*)&Bs[kk][tx * 4];
#pragma unroll
            for (int i = 0; i < 8; ++i)
#pragma unroll
                for (int j = 0; j < 4; ++j)
                    acc[i][j] += a[i] * bv[j];
        }
        __syncthreads();
    }

    float bias[4];
#pragma unroll
    for (int j = 0; j < 4; ++j) {
        int v = v0 + tx * 4 + j;
        bias[j] = (v < VSZ) ? out_b[v] : 0.0f;
    }

#pragma unroll
    for (int i = 0; i < 8; ++i) {
        unsigned long long key = 0ull;
#pragma unroll
        for (int j = 0; j < 4; ++j) {
            int v = v0 + tx * 4 + j;
            if (v < VSZ) {
                float val = acc[i][j] + bias[j];
                unsigned long long k =
                    ((unsigned long long)ford(val) << 32) | (unsigned int)(~v);
                if (k > key) key = k;
            }
        }
#pragma unroll
        for (int off = 8; off; off >>= 1) {
            unsigned long long other = __shfl_xor_sync(0xFFFFFFFFu, key, off, 16);
            if (other > key) key = other;
        }
        if (tx == 0) atomicMax(&g_amax[t & 1][ty * 8 + i], key);
    }
}

// ---------------------------------------------------------------------------
// final token write
// ---------------------------------------------------------------------------
__global__ void final_kernel(float* __restrict__ out) {
    int b = threadIdx.x;
    if (b < B) {
        int tok = (int)(~(unsigned int)(g_amax[(TLEN - 1) & 1][b]));
        out[2 * B + b * TLEN + (TLEN - 1)] = (float)tok;
    }
}

// ---------------------------------------------------------------------------
extern "C" void kernel_launch(void* const* d_in, const int* in_sizes, int n_in,
                              void* d_out, int out_size) {
    const float* fused = (const float*)d_in[0];
    const float* emb   = (const float*)d_in[1];
    const float* W_ih  = (const float*)d_in[2];
    const float* W_hh  = (const float*)d_in[3];
    const float* b_ih  = (const float*)d_in[4];
    const float* b_hh  = (const float*)d_in[5];
    const float* out_W = (const float*)d_in[6];
    const float* out_b = (const float*)d_in[7];
    const float* c1_W  = (const float*)d_in[8];
    const float* c1_b  = (const float*)d_in[9];
    const float* c2_W  = (const float*)d_in[10];
    const float* c2_b  = (const float*)d_in[11];
    float* out = (float*)d_out;

    init_kernel<<<(B * HID + 255) / 256, 256>>>(fused);
    closed1_kernel<<<C1, 64>>>(fused, c1_W, c1_b);
    closed2_kernel<<<1, 128>>>(c2_W, c2_b, out);

    for (int t = 0; t < TLEN; ++t) {
        gates_kernel<<<HID / 4, 128>>>(emb, W_ih, W_hh, b_ih, b_hh, t, out);
        logits_kernel<<<(VSZ + 63) / 64, 128>>>(out_W, out_b, t);
    }
    final_kernel<<<1, 64>>>(out);
}

// round 2
// speedup vs baseline: 1.7323x; 1.7323x over previous
#include <cuda_runtime.h>

#define B    64
#define HID  768
#define VSZ  30000
#define TLEN 32
#define C1   512
#define KS   8                 // gates split-K factor
#define KSPL (2 * HID / KS)    // 192 K per split
#define KT   16                // k-tile

__device__ float g_h[2][B * HID];
__device__ float g_c[B * HID];
__device__ float g_hidden[B * C1];
__device__ unsigned long long g_amax[2][B];
__device__ float g_gpart[KS][B][4 * HID];

__device__ __forceinline__ unsigned int ford(float f) {
    unsigned int u = __float_as_uint(f);
    return u ^ (((int)u >> 31) | 0x80000000u);
}
__device__ __forceinline__ float sigm(float x) { return 1.0f / (1.0f + expf(-x)); }

// packed f32x2 helpers
#define FMA2(c, a, b) asm("fma.rn.f32x2 %0, %1, %2, %0;" : "+l"(c) : "l"(a), "l"(b))
__device__ __forceinline__ unsigned long long pack2(float x) {
    unsigned long long r;
    unsigned int u = __float_as_uint(x);
    asm("mov.b64 %0, {%1, %1};" : "=l"(r) : "r"(u));
    return r;
}
__device__ __forceinline__ float lane_lo(unsigned long long v) {
    return __uint_as_float((unsigned int)v);
}
__device__ __forceinline__ float lane_hi(unsigned long long v) {
    return __uint_as_float((unsigned int)(v >> 32));
}

// ---------------------------------------------------------------------------
__global__ void init_kernel(const float* __restrict__ fused) {
    int i = blockIdx.x * blockDim.x + threadIdx.x;
    if (i < B * HID) {
        g_h[0][i] = fused[i];
        g_c[i] = 0.0f;
    }
    if (blockIdx.x == 0 && threadIdx.x < B) {
        g_amax[0][threadIdx.x] = 0ull;
        g_amax[1][threadIdx.x] = 0ull;
    }
}

// ---------------------------------------------------------------------------
// closed path (one-time, tiny)
// ---------------------------------------------------------------------------
__global__ void closed1_kernel(const float* __restrict__ fused,
                               const float* __restrict__ c1_W,
                               const float* __restrict__ c1_b) {
    __shared__ float w[HID];
    int j = blockIdx.x;
    for (int k = threadIdx.x; k < HID; k += 64) w[k] = c1_W[j * HID + k];
    __syncthreads();
    int b = threadIdx.x;
    float acc = 0.0f;
    for (int k = 0; k < HID; ++k) acc += fused[b * HID + k] * w[k];
    acc += c1_b[j];
    g_hidden[b * C1 + j] = fmaxf(acc, 0.0f);
}

__global__ void closed2_kernel(const float* __restrict__ c2_W,
                               const float* __restrict__ c2_b,
                               float* __restrict__ out) {
    int tid = threadIdx.x;
    int b = tid >> 1, cls = tid & 1;
    float acc = 0.0f;
    for (int k = 0; k < C1; ++k) acc += g_hidden[b * C1 + k] * c2_W[cls * C1 + k];
    out[b * 2 + cls] = acc + c2_b[cls];
}

// ---------------------------------------------------------------------------
// gates partial GEMM: block = (n-tile of 128 gate cols) x (K split of 192).
// grid = (24, 8), 256 threads, thread tile 8M x 4N via f32x2 pairs along M.
// Also: extract tok for this step, reset this step's argmax slot, write
// generated token of previous step (block (0,0) only).
// ---------------------------------------------------------------------------
__global__ void __launch_bounds__(256)
gates_kernel(const float* __restrict__ emb,
             const float* __restrict__ W_ih,
             const float* __restrict__ W_hh,
             int t, float* __restrict__ out) {
    __shared__ float As[KT][B];
    __shared__ float Bs[KT][128];
    __shared__ int tok_s[B];

    const int tid = threadIdx.x;
    const int nb = blockIdx.x;        // 0..23
    const int ks = blockIdx.y;        // 0..7
    const int KOFF = ks * KSPL;
    const float* __restrict__ h_read = g_h[t & 1];

    if (tid < B) {
        int tok = 0;
        if (t > 0) tok = (int)(~(unsigned int)(g_amax[(t - 1) & 1][tid]));
        tok_s[tid] = tok;
        g_amax[t & 1][tid] = 0ull;
        if (t > 0 && nb == 0 && ks == 0)
            out[2 * B + tid * TLEN + (t - 1)] = (float)tok;
    }
    __syncthreads();

    const int am = tid >> 2, aq = tid & 3;   // A loader: 256 float4
    const int ty = tid >> 5, tx = tid & 31;  // compute mapping

    float4 aP;
    float4 bP[2];
    int bn[2], bq[2];
#pragma unroll
    for (int j = 0; j < 2; ++j) {
        int idx = tid * 2 + j;
        bn[j] = idx >> 2;
        bq[j] = idx & 3;
    }

    // prefetch first tile
    {
        int kg = KOFF + aq * 4;
        aP = (kg < HID)
            ? *(const float4*)(emb + (size_t)tok_s[am] * HID + kg)
            : *(const float4*)(h_read + am * HID + (kg - HID));
#pragma unroll
        for (int j = 0; j < 2; ++j) {
            int c = nb * 128 + bn[j];
            int kb = KOFF + bq[j] * 4;
            bP[j] = (kb < HID)
                ? *(const float4*)(W_ih + (size_t)c * HID + kb)
                : *(const float4*)(W_hh + (size_t)c * HID + (kb - HID));
        }
    }

    unsigned long long acc[4][4];
#pragma unroll
    for (int p = 0; p < 4; ++p)
#pragma unroll
        for (int j = 0; j < 4; ++j) acc[p][j] = 0ull;

    for (int k0 = 0; k0 < KSPL; k0 += KT) {
        As[aq * 4 + 0][am] = aP.x; As[aq * 4 + 1][am] = aP.y;
        As[aq * 4 + 2][am] = aP.z; As[aq * 4 + 3][am] = aP.w;
#pragma unroll
        for (int j = 0; j < 2; ++j) {
            Bs[bq[j] * 4 + 0][bn[j]] = bP[j].x; Bs[bq[j] * 4 + 1][bn[j]] = bP[j].y;
            Bs[bq[j] * 4 + 2][bn[j]] = bP[j].z; Bs[bq[j] * 4 + 3][bn[j]] = bP[j].w;
        }
        __syncthreads();

        if (k0 + KT < KSPL) {
            int kg = KOFF + k0 + KT + aq * 4;
            aP = (kg < HID)
                ? *(const float4*)(emb + (size_t)tok_s[am] * HID + kg)
                : *(const float4*)(h_read + am * HID + (kg - HID));
#pragma unroll
            for (int j = 0; j < 2; ++j) {
                int c = nb * 128 + bn[j];
                int kb = KOFF + k0 + KT + bq[j] * 4;
                bP[j] = (kb < HID)
                    ? *(const float4*)(W_ih + (size_t)c * HID + kb)
                    : *(const float4*)(W_hh + (size_t)c * HID + (kb - HID));
            }
        }

#pragma unroll
        for (int kk = 0; kk < KT; ++kk) {
            unsigned long long ap[4];
#pragma unroll
            for (int p = 0; p < 4; ++p)
                ap[p] = *(const unsigned long long*)&As[kk][ty * 8 + p * 2];
            float4 bv = *(const float4*)&Bs[kk][tx * 4];
            unsigned long long bb[4];
            bb[0] = pack2(bv.x); bb[1] = pack2(bv.y);
            bb[2] = pack2(bv.z); bb[3] = pack2(bv.w);
#pragma unroll
            for (int p = 0; p < 4; ++p)
#pragma unroll
                for (int j = 0; j < 4; ++j)
                    FMA2(acc[p][j], ap[p], bb[j]);
        }
        __syncthreads();
    }

    // store partials (c columns, rows = batches)
    const int c0 = nb * 128 + tx * 4;
#pragma unroll
    for (int p = 0; p < 4; ++p) {
        int m0 = ty * 8 + p * 2;
        float4 lo4 = make_float4(lane_lo(acc[p][0]), lane_lo(acc[p][1]),
                                 lane_lo(acc[p][2]), lane_lo(acc[p][3]));
        float4 hi4 = make_float4(lane_hi(acc[p][0]), lane_hi(acc[p][1]),
                                 lane_hi(acc[p][2]), lane_hi(acc[p][3]));
        *(float4*)&g_gpart[ks][m0][c0]     = lo4;
        *(float4*)&g_gpart[ks][m0 + 1][c0] = hi4;
    }
}

// ---------------------------------------------------------------------------
// cell: reduce KS partials (fixed order), biases, LSTM nonlinearities
// ---------------------------------------------------------------------------
__global__ void cell_kernel(const float* __restrict__ b_ih,
                            const float* __restrict__ b_hh, int t) {
    int idx = blockIdx.x * blockDim.x + threadIdx.x;  // 0..49151
    if (idx >= B * HID) return;
    int b = idx / HID, u = idx - b * HID;

    float gi = b_ih[u] + b_hh[u];
    float gf = b_ih[HID + u] + b_hh[HID + u];
    float gg = b_ih[2 * HID + u] + b_hh[2 * HID + u];
    float go = b_ih[3 * HID + u] + b_hh[3 * HID + u];
#pragma unroll
    for (int s = 0; s < KS; ++s) {
        gi += g_gpart[s][b][u];
        gf += g_gpart[s][b][HID + u];
        gg += g_gpart[s][b][2 * HID + u];
        go += g_gpart[s][b][3 * HID + u];
    }
    float cn = sigm(gf) * g_c[idx] + sigm(gi) * tanhf(gg);
    g_c[idx] = cn;
    g_h[(t + 1) & 1][idx] = sigm(go) * tanhf(cn);
}

// ---------------------------------------------------------------------------
// logits + argmax: 64x128 block tile, 256 threads, f32x2 thread tile 8x4.
// grid = ceil(30000/128) = 235.
// ---------------------------------------------------------------------------
__global__ void __launch_bounds__(256)
logits_kernel(const float* __restrict__ out_W,
              const float* __restrict__ out_b, int t) {
    __shared__ float As[KT][B];
    __shared__ float Bs[KT][128];
    const float* __restrict__ h_read = g_h[(t + 1) & 1];

    const int tid = threadIdx.x;
    const int v0 = blockIdx.x * 128;
    const int am = tid >> 2, aq = tid & 3;
    const int ty = tid >> 5, tx = tid & 31;

    int bn[2], bq[2];
#pragma unroll
    for (int j = 0; j < 2; ++j) {
        int idx = tid * 2 + j;
        bn[j] = idx >> 2;
        bq[j] = idx & 3;
    }

    float4 aP = *(const float4*)(h_read + am * HID + aq * 4);
    float4 bP[2];
#pragma unroll
    for (int j = 0; j < 2; ++j) {
        int v = v0 + bn[j];
        bP[j] = (v < VSZ) ? *(const float4*)(out_W + (size_t)v * HID + bq[j] * 4)
                          : make_float4(0.f, 0.f, 0.f, 0.f);
    }

    unsigned long long acc[4][4];
#pragma unroll
    for (int p = 0; p < 4; ++p)
#pragma unroll
        for (int j = 0; j < 4; ++j) acc[p][j] = 0ull;

    for (int k0 = 0; k0 < HID; k0 += KT) {
        As[aq * 4 + 0][am] = aP.x; As[aq * 4 + 1][am] = aP.y;
        As[aq * 4 + 2][am] = aP.z; As[aq * 4 + 3][am] = aP.w;
#pragma unroll
        for (int j = 0; j < 2; ++j) {
            Bs[bq[j] * 4 + 0][bn[j]] = bP[j].x; Bs[bq[j] * 4 + 1][bn[j]] = bP[j].y;
            Bs[bq[j] * 4 + 2][bn[j]] = bP[j].z; Bs[bq[j] * 4 + 3][bn[j]] = bP[j].w;
        }
        __syncthreads();

        if (k0 + KT < HID) {
            aP = *(const float4*)(h_read + am * HID + k0 + KT + aq * 4);
#pragma unroll
            for (int j = 0; j < 2; ++j) {
                int v = v0 + bn[j];
                bP[j] = (v < VSZ)
                    ? *(const float4*)(out_W + (size_t)v * HID + k0 + KT + bq[j] * 4)
                    : make_float4(0.f, 0.f, 0.f, 0.f);
            }
        }

#pragma unroll
        for (int kk = 0; kk < KT; ++kk) {
            unsigned long long ap[4];
#pragma unroll
            for (int p = 0; p < 4; ++p)
                ap[p] = *(const unsigned long long*)&As[kk][ty * 8 + p * 2];
            float4 bv = *(const float4*)&Bs[kk][tx * 4];
            unsigned long long bb[4];
            bb[0] = pack2(bv.x); bb[1] = pack2(bv.y);
            bb[2] = pack2(bv.z); bb[3] = pack2(bv.w);
#pragma unroll
            for (int p = 0; p < 4; ++p)
#pragma unroll
                for (int j = 0; j < 4; ++j)
                    FMA2(acc[p][j], ap[p], bb[j]);
        }
        __syncthreads();
    }

    float bias[4];
#pragma unroll
    for (int j = 0; j < 4; ++j) {
        int v = v0 + tx * 4 + j;
        bias[j] = (v < VSZ) ? out_b[v] : 0.0f;
    }

    // per-warp (= per 8 batch rows) argmax over this block's 128 columns
#pragma unroll
    for (int p = 0; p < 4; ++p) {
#pragma unroll
        for (int hh = 0; hh < 2; ++hh) {
            int m = ty * 8 + p * 2 + hh;
            unsigned long long key = 0ull;
#pragma unroll
            for (int j = 0; j < 4; ++j) {
                int v = v0 + tx * 4 + j;
                if (v < VSZ) {
                    float val = (hh ? lane_hi(acc[p][j]) : lane_lo(acc[p][j])) + bias[j];
                    unsigned long long k =
                        ((unsigned long long)ford(val) << 32) | (unsigned int)(~v);
                    if (k > key) key = k;
                }
            }
#pragma unroll
            for (int off = 16; off; off >>= 1) {
                unsigned long long other = __shfl_xor_sync(0xFFFFFFFFu, key, off);
                if (other > key) key = other;
            }
            if (tx == 0) atomicMax(&g_amax[t & 1][m], key);
        }
    }
}

// ---------------------------------------------------------------------------
__global__ void final_kernel(float* __restrict__ out) {
    int b = threadIdx.x;
    if (b < B) {
        int tok = (int)(~(unsigned int)(g_amax[(TLEN - 1) & 1][b]));
        out[2 * B + b * TLEN + (TLEN - 1)] = (float)tok;
    }
}

// ---------------------------------------------------------------------------
extern "C" void kernel_launch(void* const* d_in, const int* in_sizes, int n_in,
                              void* d_out, int out_size) {
    const float* fused = (const float*)d_in[0];
    const float* emb   = (const float*)d_in[1];
    const float* W_ih  = (const float*)d_in[2];
    const float* W_hh  = (const float*)d_in[3];
    const float* b_ih  = (const float*)d_in[4];
    const float* b_hh  = (const float*)d_in[5];
    const float* out_W = (const float*)d_in[6];
    const float* out_b = (const float*)d_in[7];
    const float* c1_W  = (const float*)d_in[8];
    const float* c1_b  = (const float*)d_in[9];
    const float* c2_W  = (const float*)d_in[10];
    const float* c2_b  = (const float*)d_in[11];
    float* out = (float*)d_out;

    init_kernel<<<(B * HID + 255) / 256, 256>>>(fused);
    closed1_kernel<<<C1, 64>>>(fused, c1_W, c1_b);
    closed2_kernel<<<1, 128>>>(c2_W, c2_b, out);

    dim3 ggrid(4 * HID / 128, KS);
    for (int t = 0; t < TLEN; ++t) {
        gates_kernel<<<ggrid, 256>>>(emb, W_ih, W_hh, t, out);
        cell_kernel<<<(B * HID + 255) / 256, 256>>>(b_ih, b_hh, t);
        logits_kernel<<<(VSZ + 127) / 128, 256>>>(out_W, out_b, t);
    }
    final_kernel<<<1, 64>>>(out);
}

// round 6
// speedup vs baseline: 3.0961x; 1.7872x over previous
#include <cuda_runtime.h>
#include <cuda_bf16.h>
#include <cstdint>

#define B    64
#define HID  768
#define VSZ  30000
#define TLEN 32
#define C1   512
#define KS   8
#define KSPL (2 * HID / KS)
#define KT   16

// HMMA logits tiling
#define MT      64
#define KC      64                      // k per chunk (128 bytes of bf16)
#define NCHUNK  (HID / KC)              // 12
#define GRID_L  ((VSZ + MT - 1) / MT)   // 469

__device__ float g_h[2][B * HID];
__device__ float g_c[B * HID];
__device__ float g_hidden[B * C1];
__device__ unsigned long long g_amax[2][B];
__device__ float g_gpart[KS][B][4 * HID];
__device__ __nv_bfloat16 g_Whi[(size_t)VSZ * HID];
__device__ __nv_bfloat16 g_Wlo[(size_t)VSZ * HID];
__device__ __nv_bfloat16 g_hhi[B * HID];
__device__ __nv_bfloat16 g_hlo[B * HID];

__device__ __forceinline__ unsigned int ford(float f) {
    unsigned int u = __float_as_uint(f);
    return u ^ (((int)u >> 31) | 0x80000000u);
}
__device__ __forceinline__ float sigm(float x) { return 1.0f / (1.0f + expf(-x)); }

// ---- packed f32x2 (gates GEMM) ----
#define FMA2(c, a, b) asm("fma.rn.f32x2 %0, %1, %2, %0;" : "+l"(c) : "l"(a), "l"(b))
__device__ __forceinline__ unsigned long long pack2(float x) {
    unsigned long long r;
    unsigned int u = __float_as_uint(x);
    asm("mov.b64 %0, {%1, %1};" : "=l"(r) : "r"(u));
    return r;
}
__device__ __forceinline__ float lane_lo(unsigned long long v) { return __uint_as_float((unsigned int)v); }
__device__ __forceinline__ float lane_hi(unsigned long long v) { return __uint_as_float((unsigned int)(v >> 32)); }

__device__ __forceinline__ uint32_t smem_u32(const void* p) {
    uint32_t a;
    asm("{ .reg .u64 t; cvta.to.shared.u64 t, %1; cvt.u32.u64 %0, t; }" : "=r"(a) : "l"(p));
    return a;
}

#define LDSM4(r0, r1, r2, r3, addr) \
    asm volatile("ldmatrix.sync.aligned.m8n8.x4.shared.b16 {%0,%1,%2,%3}, [%4];" \
                 : "=r"(r0), "=r"(r1), "=r"(r2), "=r"(r3) : "r"(addr))

#define MMA16816(d, a, bf) \
    asm volatile("mma.sync.aligned.m16n8k16.row.col.f32.bf16.bf16.f32 " \
                 "{%0,%1,%2,%3}, {%4,%5,%6,%7}, {%8,%9}, {%0,%1,%2,%3};" \
                 : "+f"((d)[0]), "+f"((d)[1]), "+f"((d)[2]), "+f"((d)[3]) \
                 : "r"((a)[0]), "r"((a)[1]), "r"((a)[2]), "r"((a)[3]), \
                   "r"((bf)[0]), "r"((bf)[1]))

// ---------------------------------------------------------------------------
__global__ void init_kernel(const float* __restrict__ fused) {
    int i = blockIdx.x * blockDim.x + threadIdx.x;
    if (i < B * HID) {
        g_h[0][i] = fused[i];
        g_c[i] = 0.0f;
    }
    if (blockIdx.x == 0 && threadIdx.x < B) {
        g_amax[0][threadIdx.x] = 0ull;
        g_amax[1][threadIdx.x] = 0ull;
    }
}

// ---------------------------------------------------------------------------
// one-time: split out_W into bf16 hi/lo
// ---------------------------------------------------------------------------
__global__ void wsplit_kernel(const float* __restrict__ w) {
    size_t n = (size_t)VSZ * HID;
    size_t stride = (size_t)gridDim.x * blockDim.x * 4;
    for (size_t i = ((size_t)blockIdx.x * blockDim.x + threadIdx.x) * 4; i < n; i += stride) {
        float4 x = *(const float4*)(w + i);
        __nv_bfloat16 h0 = __float2bfloat16(x.x);
        __nv_bfloat16 h1 = __float2bfloat16(x.y);
        __nv_bfloat16 h2 = __float2bfloat16(x.z);
        __nv_bfloat16 h3 = __float2bfloat16(x.w);
        g_Whi[i] = h0; g_Whi[i + 1] = h1; g_Whi[i + 2] = h2; g_Whi[i + 3] = h3;
        g_Wlo[i]     = __float2bfloat16(x.x - __bfloat162float(h0));
        g_Wlo[i + 1] = __float2bfloat16(x.y - __bfloat162float(h1));
        g_Wlo[i + 2] = __float2bfloat16(x.z - __bfloat162float(h2));
        g_Wlo[i + 3] = __float2bfloat16(x.w - __bfloat162float(h3));
    }
}

// ---------------------------------------------------------------------------
// closed path (one-time, tiny)
// ---------------------------------------------------------------------------
__global__ void closed1_kernel(const float* __restrict__ fused,
                               const float* __restrict__ c1_W,
                               const float* __restrict__ c1_b) {
    __shared__ float w[HID];
    int j = blockIdx.x;
    for (int k = threadIdx.x; k < HID; k += 64) w[k] = c1_W[j * HID + k];
    __syncthreads();
    int b = threadIdx.x;
    float acc = 0.0f;
    for (int k = 0; k < HID; ++k) acc += fused[b * HID + k] * w[k];
    acc += c1_b[j];
    g_hidden[b * C1 + j] = fmaxf(acc, 0.0f);
}

__global__ void closed2_kernel(const float* __restrict__ c2_W,
                               const float* __restrict__ c2_b,
                               float* __restrict__ out) {
    int tid = threadIdx.x;
    int b = tid >> 1, cls = tid & 1;
    float acc = 0.0f;
    for (int k = 0; k < C1; ++k) acc += g_hidden[b * C1 + k] * c2_W[cls * C1 + k];
    out[b * 2 + cls] = acc + c2_b[cls];
}

// ---------------------------------------------------------------------------
// gates partial GEMM (FFMA2), unchanged
// ---------------------------------------------------------------------------
__global__ void __launch_bounds__(256)
gates_kernel(const float* __restrict__ emb,
             const float* __restrict__ W_ih,
             const float* __restrict__ W_hh,
             int t, float* __restrict__ out) {
    __shared__ float As[KT][B];
    __shared__ float Bs[KT][128];
    __shared__ int tok_s[B];

    const int tid = threadIdx.x;
    const int nb = blockIdx.x;
    const int ks = blockIdx.y;
    const int KOFF = ks * KSPL;
    const float* __restrict__ h_read = g_h[t & 1];

    if (tid < B) {
        int tok = 0;
        if (t > 0) tok = (int)(~(unsigned int)(g_amax[(t - 1) & 1][tid]));
        tok_s[tid] = tok;
        g_amax[t & 1][tid] = 0ull;
        if (t > 0 && nb == 0 && ks == 0)
            out[2 * B + tid * TLEN + (t - 1)] = (float)tok;
    }
    __syncthreads();

    const int am = tid >> 2, aq = tid & 3;
    const int ty = tid >> 5, tx = tid & 31;

    float4 aP;
    float4 bP[2];
    int bn[2], bq[2];
#pragma unroll
    for (int j = 0; j < 2; ++j) {
        int idx = tid * 2 + j;
        bn[j] = idx >> 2;
        bq[j] = idx & 3;
    }

    {
        int kg = KOFF + aq * 4;
        aP = (kg < HID)
            ? *(const float4*)(emb + (size_t)tok_s[am] * HID + kg)
            : *(const float4*)(h_read + am * HID + (kg - HID));
#pragma unroll
        for (int j = 0; j < 2; ++j) {
            int c = nb * 128 + bn[j];
            int kb = KOFF + bq[j] * 4;
            bP[j] = (kb < HID)
                ? *(const float4*)(W_ih + (size_t)c * HID + kb)
                : *(const float4*)(W_hh + (size_t)c * HID + (kb - HID));
        }
    }

    unsigned long long acc[4][4];
#pragma unroll
    for (int p = 0; p < 4; ++p)
#pragma unroll
        for (int j = 0; j < 4; ++j) acc[p][j] = 0ull;

    for (int k0 = 0; k0 < KSPL; k0 += KT) {
        As[aq * 4 + 0][am] = aP.x; As[aq * 4 + 1][am] = aP.y;
        As[aq * 4 + 2][am] = aP.z; As[aq * 4 + 3][am] = aP.w;
#pragma unroll
        for (int j = 0; j < 2; ++j) {
            Bs[bq[j] * 4 + 0][bn[j]] = bP[j].x; Bs[bq[j] * 4 + 1][bn[j]] = bP[j].y;
            Bs[bq[j] * 4 + 2][bn[j]] = bP[j].z; Bs[bq[j] * 4 + 3][bn[j]] = bP[j].w;
        }
        __syncthreads();

        if (k0 + KT < KSPL) {
            int kg = KOFF + k0 + KT + aq * 4;
            aP = (kg < HID)
                ? *(const float4*)(emb + (size_t)tok_s[am] * HID + kg)
                : *(const float4*)(h_read + am * HID + (kg - HID));
#pragma unroll
            for (int j = 0; j < 2; ++j) {
                int c = nb * 128 + bn[j];
                int kb = KOFF + k0 + KT + bq[j] * 4;
                bP[j] = (kb < HID)
                    ? *(const float4*)(W_ih + (size_t)c * HID + kb)
                    : *(const float4*)(W_hh + (size_t)c * HID + (kb - HID));
            }
        }

#pragma unroll
        for (int kk = 0; kk < KT; ++kk) {
            unsigned long long ap[4];
#pragma unroll
            for (int p = 0; p < 4; ++p)
                ap[p] = *(const unsigned long long*)&As[kk][ty * 8 + p * 2];
            float4 bv = *(const float4*)&Bs[kk][tx * 4];
            unsigned long long bb[4];
            bb[0] = pack2(bv.x); bb[1] = pack2(bv.y);
            bb[2] = pack2(bv.z); bb[3] = pack2(bv.w);
#pragma unroll
            for (int p = 0; p < 4; ++p)
#pragma unroll
                for (int j = 0; j < 4; ++j)
                    FMA2(acc[p][j], ap[p], bb[j]);
        }
        __syncthreads();
    }

    const int c0 = nb * 128 + tx * 4;
#pragma unroll
    for (int p = 0; p < 4; ++p) {
        int m0 = ty * 8 + p * 2;
        float4 lo4 = make_float4(lane_lo(acc[p][0]), lane_lo(acc[p][1]),
                                 lane_lo(acc[p][2]), lane_lo(acc[p][3]));
        float4 hi4 = make_float4(lane_hi(acc[p][0]), lane_hi(acc[p][1]),
                                 lane_hi(acc[p][2]), lane_hi(acc[p][3]));
        *(float4*)&g_gpart[ks][m0][c0]     = lo4;
        *(float4*)&g_gpart[ks][m0 + 1][c0] = hi4;
    }
}

// ---------------------------------------------------------------------------
// cell: reduce partials, LSTM nonlinearities, emit h and bf16 hi/lo split
// ---------------------------------------------------------------------------
__global__ void cell_kernel(const float* __restrict__ b_ih,
                            const float* __restrict__ b_hh, int t) {
    int idx = blockIdx.x * blockDim.x + threadIdx.x;
    if (idx >= B * HID) return;
    int b = idx / HID, u = idx - b * HID;

    float gi = b_ih[u] + b_hh[u];
    float gf = b_ih[HID + u] + b_hh[HID + u];
    float gg = b_ih[2 * HID + u] + b_hh[2 * HID + u];
    float go = b_ih[3 * HID + u] + b_hh[3 * HID + u];
#pragma unroll
    for (int s = 0; s < KS; ++s) {
        gi += g_gpart[s][b][u];
        gf += g_gpart[s][b][HID + u];
        gg += g_gpart[s][b][2 * HID + u];
        go += g_gpart[s][b][3 * HID + u];
    }
    float cn = sigm(gf) * g_c[idx] + sigm(gi) * tanhf(gg);
    g_c[idx] = cn;
    float hn = sigm(go) * tanhf(cn);
    g_h[(t + 1) & 1][idx] = hn;
    __nv_bfloat16 hi = __float2bfloat16(hn);
    g_hhi[idx] = hi;
    g_hlo[idx] = __float2bfloat16(hn - __bfloat162float(hi));
}

// ---------------------------------------------------------------------------
// logits via mma.sync bf16 split: D[64 vocab x 64 batch] =
//   Whi*hhi + Whi*hlo + Wlo*hhi   (fp32 accum), then bias + argmax.
// 256 threads = 8 warps in 4(M) x 2(N); warp tile m16 x n32; K chunks of 64.
// SMEM rows are 128B with XOR-16B swizzle for conflict-free ldmatrix.
// ---------------------------------------------------------------------------
__global__ void __launch_bounds__(256, 2)
logits_mma(const float* __restrict__ out_b, int t) {
    __shared__ __align__(128) __nv_bfloat16 sWhi[MT * KC];
    __shared__ __align__(128) __nv_bfloat16 sWlo[MT * KC];
    __shared__ __align__(128) __nv_bfloat16 sHhi[B * KC];
    __shared__ __align__(128) __nv_bfloat16 sHlo[B * KC];
    __shared__ unsigned long long skeys[4][B];

    const int tid = threadIdx.x, wid = tid >> 5, lane = tid & 31;
    const int mw = wid >> 1, nw = wid & 1;
    const int v0 = blockIdx.x * MT;

    // --- loader setup: 2048 uint4 per chunk, 8 per thread ---
    const __nv_bfloat16* srcp[8];
    uint32_t dsta[8];
#pragma unroll
    for (int i = 0; i < 8; ++i) {
        int s = tid + i * 256;
        int r = (s & 511) >> 3, g = s & 7;
        uint32_t dst = (uint32_t)(r * 128 + ((g ^ (r & 7)) * 16));
        if (s < 512) {
            int v = v0 + r; if (v >= VSZ) v = VSZ - 1;
            srcp[i] = g_Whi + (size_t)v * HID + g * 8;
            dsta[i] = smem_u32(sWhi) + dst;
        } else if (s < 1024) {
            int v = v0 + r; if (v >= VSZ) v = VSZ - 1;
            srcp[i] = g_Wlo + (size_t)v * HID + g * 8;
            dsta[i] = smem_u32(sWlo) + dst;
        } else if (s < 1536) {
            srcp[i] = g_hhi + r * HID + g * 8;
            dsta[i] = smem_u32(sHhi) + dst;
        } else {
            srcp[i] = g_hlo + r * HID + g * 8;
            dsta[i] = smem_u32(sHlo) + dst;
        }
    }

    // --- ldmatrix address components (fixed per thread; g varies per step) ---
    const int mA = mw * 16 + ((lane >> 3) & 1) * 8 + (lane & 7);  // A row in tile
    const int gAo = lane >> 4;                                    // 0/1 k-group
    const int nB = nw * 32 + ((lane >> 4) & 1) * 8 + (lane & 7);  // B row base (ntpair adds 16)
    const int gBo = (lane >> 3) & 1;
    const uint32_t sWhiB = smem_u32(sWhi), sWloB = smem_u32(sWlo);
    const uint32_t sHhiB = smem_u32(sHhi), sHloB = smem_u32(sHlo);

    float acc[4][4];
#pragma unroll
    for (int n = 0; n < 4; ++n)
#pragma unroll
        for (int j = 0; j < 4; ++j) acc[n][j] = 0.0f;

    uint4 pf[8];
#pragma unroll
    for (int i = 0; i < 8; ++i) { pf[i] = *(const uint4*)srcp[i]; srcp[i] += KC; }

    for (int c = 0; c < NCHUNK; ++c) {
#pragma unroll
        for (int i = 0; i < 8; ++i)
            asm volatile("st.shared.v4.b32 [%0], {%1, %2, %3, %4};"
                         :: "r"(dsta[i]), "r"(pf[i].x), "r"(pf[i].y),
                            "r"(pf[i].z), "r"(pf[i].w) : "memory");
        __syncthreads();

        if (c + 1 < NCHUNK) {
#pragma unroll
            for (int i = 0; i < 8; ++i) { pf[i] = *(const uint4*)srcp[i]; srcp[i] += KC; }
        }

#pragma unroll
        for (int step = 0; step < 4; ++step) {
            const int g0 = step * 2;
            const int gA = g0 + gAo;
            const uint32_t offA = (uint32_t)(mA * 128 + ((gA ^ (mA & 7)) * 16));
            uint32_t ahi[4], alo[4];
            LDSM4(ahi[0], ahi[1], ahi[2], ahi[3], sWhiB + offA);
            LDSM4(alo[0], alo[1], alo[2], alo[3], sWloB + offA);

            uint32_t bhi[4][2], blo[4][2];
#pragma unroll
            for (int ntp = 0; ntp < 2; ++ntp) {
                const int nr = nB + ntp * 16;
                const int gB = g0 + gBo;
                const uint32_t offB = (uint32_t)(nr * 128 + ((gB ^ (nr & 7)) * 16));
                LDSM4(bhi[ntp * 2][0], bhi[ntp * 2][1],
                      bhi[ntp * 2 + 1][0], bhi[ntp * 2 + 1][1], sHhiB + offB);
                LDSM4(blo[ntp * 2][0], blo[ntp * 2][1],
                      blo[ntp * 2 + 1][0], blo[ntp * 2 + 1][1], sHloB + offB);
            }
#pragma unroll
            for (int n = 0; n < 4; ++n) {
                MMA16816(acc[n], ahi, bhi[n]);
                MMA16816(acc[n], ahi, blo[n]);
                MMA16816(acc[n], alo, bhi[n]);
            }
        }
        __syncthreads();
    }

    // --- epilogue: bias + deterministic argmax ---
    const int laneg = lane >> 2, lane4 = lane & 3;
    const int m_lo = v0 + mw * 16 + laneg;
    const int m_hi = m_lo + 8;
    const bool val_lo = m_lo < VSZ, val_hi = m_hi < VSZ;
    const float bias_lo = val_lo ? out_b[m_lo] : 0.0f;
    const float bias_hi = val_hi ? out_b[m_hi] : 0.0f;
    const unsigned int ni_lo = ~(unsigned int)m_lo, ni_hi = ~(unsigned int)m_hi;

#pragma unroll
    for (int n = 0; n < 4; ++n) {
        unsigned long long kA = 0ull, kB = 0ull;
        if (val_lo) {
            kA = ((unsigned long long)ford(acc[n][0] + bias_lo) << 32) | ni_lo;
            kB = ((unsigned long long)ford(acc[n][1] + bias_lo) << 32) | ni_lo;
        }
        if (val_hi) {
            unsigned long long k2 = ((unsigned long long)ford(acc[n][2] + bias_hi) << 32) | ni_hi;
            unsigned long long k3 = ((unsigned long long)ford(acc[n][3] + bias_hi) << 32) | ni_hi;
            if (k2 > kA) kA = k2;
            if (k3 > kB) kB = k3;
        }
#pragma unroll
        for (int off = 4; off < 32; off <<= 1) {
            unsigned long long oA = __shfl_xor_sync(0xFFFFFFFFu, kA, off);
            unsigned long long oB = __shfl_xor_sync(0xFFFFFFFFu, kB, off);
            if (oA > kA) kA = oA;
            if (oB > kB) kB = oB;
        }
        if (laneg == 0) {
            int ncol = nw * 32 + n * 8 + lane4 * 2;
            skeys[mw][ncol]     = kA;
            skeys[mw][ncol + 1] = kB;
        }
    }
    __syncthreads();
    if (tid < B) {
        unsigned long long k = skeys[0][tid];
        if (skeys[1][tid] > k) k = skeys[1][tid];
        if (skeys[2][tid] > k) k = skeys[2][tid];
        if (skeys[3][tid] > k) k = skeys[3][tid];
        atomicMax(&g_amax[t & 1][tid], k);
    }
}

// ---------------------------------------------------------------------------
__global__ void final_kernel(float* __restrict__ out) {
    int b = threadIdx.x;
    if (b < B) {
        int tok = (int)(~(unsigned int)(g_amax[(TLEN - 1) & 1][b]));
        out[2 * B + b * TLEN + (TLEN - 1)] = (float)tok;
    }
}

// ---------------------------------------------------------------------------
extern "C" void kernel_launch(void* const* d_in, const int* in_sizes, int n_in,
                              void* d_out, int out_size) {
    const float* fused = (const float*)d_in[0];
    const float* emb   = (const float*)d_in[1];
    const float* W_ih  = (const float*)d_in[2];
    const float* W_hh  = (const float*)d_in[3];
    const float* b_ih  = (const float*)d_in[4];
    const float* b_hh  = (const float*)d_in[5];
    const float* out_W = (const float*)d_in[6];
    const float* out_b = (const float*)d_in[7];
    const float* c1_W  = (const float*)d_in[8];
    const float* c1_b  = (const float*)d_in[9];
    const float* c2_W  = (const float*)d_in[10];
    const float* c2_b  = (const float*)d_in[11];
    float* out = (float*)d_out;

    init_kernel<<<(B * HID + 255) / 256, 256>>>(fused);
    wsplit_kernel<<<2048, 256>>>(out_W);
    closed1_kernel<<<C1, 64>>>(fused, c1_W, c1_b);
    closed2_kernel<<<1, 128>>>(c2_W, c2_b, out);

    dim3 ggrid(4 * HID / 128, KS);
    for (int t = 0; t < TLEN; ++t) {
        gates_kernel<<<ggrid, 256>>>(emb, W_ih, W_hh, t, out);
        cell_kernel<<<(B * HID + 255) / 256, 256>>>(b_ih, b_hh, t);
        logits_mma<<<GRID_L, 256>>>(out_b, t);
    }
    final_kernel<<<1, 64>>>(out);
}

// round 7
// speedup vs baseline: 3.4523x; 1.1151x over previous
#include <cuda_runtime.h>
#include <cuda_bf16.h>
#include <cstdint>

#define B    64
#define HID  768
#define VSZ  30000
#define TLEN 32
#define C1   512

// logits HMMA tiling
#define MT      128
#define KC      64
#define NCHUNK  (HID / KC)              // 12
#define GRID_L  ((VSZ + MT - 1) / MT)   // 235
#define LSTAGE  49152                   // Whi 16K | Wlo 16K | Hhi 8K | Hlo 8K

// gates HMMA tiling
#define KSG     4                       // split-K
#define CHG     6                       // chunks of 64 per split (384 k)

__device__ float g_c[B * HID];          // transposed: [u][b]
__device__ float g_hidden[B * C1];
__device__ unsigned long long g_amax[2][B];
__device__ float g_gpartT[KSG][4 * HID][B];
__device__ __nv_bfloat16 g_Whi[(size_t)VSZ * HID];
__device__ __nv_bfloat16 g_Wlo[(size_t)VSZ * HID];
__device__ __nv_bfloat16 g_Ehi[(size_t)VSZ * HID];
__device__ __nv_bfloat16 g_Elo[(size_t)VSZ * HID];
__device__ __nv_bfloat16 g_WihHi[4 * HID * HID];
__device__ __nv_bfloat16 g_WihLo[4 * HID * HID];
__device__ __nv_bfloat16 g_WhhHi[4 * HID * HID];
__device__ __nv_bfloat16 g_WhhLo[4 * HID * HID];
__device__ __nv_bfloat16 g_hhi[B * HID];
__device__ __nv_bfloat16 g_hlo[B * HID];

__device__ __forceinline__ unsigned int ford(float f) {
    unsigned int u = __float_as_uint(f);
    return u ^ (((int)u >> 31) | 0x80000000u);
}
__device__ __forceinline__ float sigm(float x) { return 1.0f / (1.0f + expf(-x)); }

__device__ __forceinline__ uint32_t smem_u32(const void* p) {
    uint32_t a;
    asm("{ .reg .u64 t; cvta.to.shared.u64 t, %1; cvt.u32.u64 %0, t; }" : "=r"(a) : "l"(p));
    return a;
}

#define LDSM4(r0, r1, r2, r3, addr) \
    asm volatile("ldmatrix.sync.aligned.m8n8.x4.shared.b16 {%0,%1,%2,%3}, [%4];" \
                 : "=r"(r0), "=r"(r1), "=r"(r2), "=r"(r3) : "r"(addr))

#define MMA16816(d, a, bf) \
    asm volatile("mma.sync.aligned.m16n8k16.row.col.f32.bf16.bf16.f32 " \
                 "{%0,%1,%2,%3}, {%4,%5,%6,%7}, {%8,%9}, {%0,%1,%2,%3};" \
                 : "+f"((d)[0]), "+f"((d)[1]), "+f"((d)[2]), "+f"((d)[3]) \
                 : "r"((a)[0]), "r"((a)[1]), "r"((a)[2]), "r"((a)[3]), \
                   "r"((bf)[0]), "r"((bf)[1]))

#define CPASYNC(dst, src) \
    asm volatile("cp.async.ca.shared.global [%0], [%1], 16;" :: "r"(dst), "l"(src) : "memory")
#define CPCOMMIT() asm volatile("cp.async.commit_group;" ::: "memory")
#define CPWAIT1()  asm volatile("cp.async.wait_group 1;" ::: "memory")
#define CPWAIT0()  asm volatile("cp.async.wait_group 0;" ::: "memory")

// ---------------------------------------------------------------------------
__global__ void init_kernel(const float* __restrict__ fused) {
    int i = blockIdx.x * blockDim.x + threadIdx.x;
    if (i < B * HID) {
        float v = fused[i];
        __nv_bfloat16 hi = __float2bfloat16(v);
        g_hhi[i] = hi;
        g_hlo[i] = __float2bfloat16(v - __bfloat162float(hi));
        g_c[i] = 0.0f;
    }
    if (blockIdx.x == 0 && threadIdx.x < B) {
        g_amax[0][threadIdx.x] = 0ull;
        g_amax[1][threadIdx.x] = 0ull;
    }
}

// ---------------------------------------------------------------------------
// generic fp32 -> bf16 hi/lo split
// ---------------------------------------------------------------------------
__global__ void split_kernel(const float* __restrict__ src,
                             __nv_bfloat16* __restrict__ hi,
                             __nv_bfloat16* __restrict__ lo, size_t n) {
    size_t stride = (size_t)gridDim.x * blockDim.x * 4;
    for (size_t i = ((size_t)blockIdx.x * blockDim.x + threadIdx.x) * 4; i < n; i += stride) {
        float4 x = *(const float4*)(src + i);
        __nv_bfloat16 h0 = __float2bfloat16(x.x);
        __nv_bfloat16 h1 = __float2bfloat16(x.y);
        __nv_bfloat16 h2 = __float2bfloat16(x.z);
        __nv_bfloat16 h3 = __float2bfloat16(x.w);
        hi[i] = h0; hi[i + 1] = h1; hi[i + 2] = h2; hi[i + 3] = h3;
        lo[i]     = __float2bfloat16(x.x - __bfloat162float(h0));
        lo[i + 1] = __float2bfloat16(x.y - __bfloat162float(h1));
        lo[i + 2] = __float2bfloat16(x.z - __bfloat162float(h2));
        lo[i + 3] = __float2bfloat16(x.w - __bfloat162float(h3));
    }
}

// ---------------------------------------------------------------------------
// closed path (one-time)
// ---------------------------------------------------------------------------
__global__ void closed1_kernel(const float* __restrict__ fused,
                               const float* __restrict__ c1_W,
                               const float* __restrict__ c1_b) {
    __shared__ float w[HID];
    int j = blockIdx.x;
    for (int k = threadIdx.x; k < HID; k += 64) w[k] = c1_W[j * HID + k];
    __syncthreads();
    int b = threadIdx.x;
    float acc = 0.0f;
    for (int k = 0; k < HID; ++k) acc += fused[b * HID + k] * w[k];
    acc += c1_b[j];
    g_hidden[b * C1 + j] = fmaxf(acc, 0.0f);
}

__global__ void closed2_kernel(const float* __restrict__ c2_W,
                               const float* __restrict__ c2_b,
                               float* __restrict__ out) {
    int wid = threadIdx.x >> 5, lane = threadIdx.x & 31;
    int o = blockIdx.x * 4 + wid;         // 0..127
    int b = o >> 1, cls = o & 1;
    float acc = 0.0f;
    for (int k = lane; k < C1; k += 32)
        acc += g_hidden[b * C1 + k] * c2_W[cls * C1 + k];
#pragma unroll
    for (int off = 16; off; off >>= 1)
        acc += __shfl_xor_sync(0xFFFFFFFFu, acc, off);
    if (lane == 0) out[b * 2 + cls] = acc + c2_b[cls];
}

// ---------------------------------------------------------------------------
// gates via HMMA split-bf16: partial = Whi*xhi + Whi*xlo + Wlo*xhi
// M tile = 64 gate cols, N = 64 batch, split-K=4 (each split pure x or pure h).
// grid = (48, 4), 256 threads. Partials -> g_gpartT[ks][gatecol][batch].
// ---------------------------------------------------------------------------
__global__ void __launch_bounds__(256, 2)
gates_mma(int t, float* __restrict__ out) {
    __shared__ __align__(128) __nv_bfloat16 sAhi[64 * KC];
    __shared__ __align__(128) __nv_bfloat16 sAlo[64 * KC];
    __shared__ __align__(128) __nv_bfloat16 sBhi[B * KC];
    __shared__ __align__(128) __nv_bfloat16 sBlo[B * KC];
    __shared__ int tok_s[B];

    const int tid = threadIdx.x, wid = tid >> 5, lane = tid & 31;
    const int mw = wid >> 1, nw = wid & 1;
    const int mtile = blockIdx.x;         // 0..47
    const int ks = blockIdx.y;            // 0..3
    const bool is_x = ks < 2;
    const int kbase = (ks & 1) * 384;     // offset within the 768-wide half

    if (tid < B) {
        int tok = 0;
        if (t > 0) tok = (int)(~(unsigned int)(g_amax[(t - 1) & 1][tid]));
        tok_s[tid] = tok;
        if (mtile == 0 && ks == 0) {
            g_amax[t & 1][tid] = 0ull;
            if (t > 0) out[2 * B + tid * TLEN + (t - 1)] = (float)tok;
        }
    }
    __syncthreads();

    // loader: 2048 uint4 per chunk, 8 per thread
    const __nv_bfloat16* srcp[8];
    uint32_t dsta[8];
#pragma unroll
    for (int i = 0; i < 8; ++i) {
        int s = tid + i * 256;
        int r = (s & 511) >> 3, g = s & 7;
        uint32_t dst = (uint32_t)(r * 128 + ((g ^ (r & 7)) * 16));
        if (s < 512) {
            int m = mtile * 64 + r;
            srcp[i] = (is_x ? g_WihHi : g_WhhHi) + (size_t)m * HID + kbase + g * 8;
            dsta[i] = smem_u32(sAhi) + dst;
        } else if (s < 1024) {
            int m = mtile * 64 + r;
            srcp[i] = (is_x ? g_WihLo : g_WhhLo) + (size_t)m * HID + kbase + g * 8;
            dsta[i] = smem_u32(sAlo) + dst;
        } else if (s < 1536) {
            srcp[i] = is_x ? (g_Ehi + (size_t)tok_s[r] * HID + kbase + g * 8)
                           : (g_hhi + r * HID + kbase + g * 8);
            dsta[i] = smem_u32(sBhi) + dst;
        } else {
            srcp[i] = is_x ? (g_Elo + (size_t)tok_s[r] * HID + kbase + g * 8)
                           : (g_hlo + r * HID + kbase + g * 8);
            dsta[i] = smem_u32(sBlo) + dst;
        }
    }

    const int mA = mw * 16 + ((lane >> 3) & 1) * 8 + (lane & 7);
    const int gAo = lane >> 4;
    const int nB = nw * 32 + ((lane >> 4) & 1) * 8 + (lane & 7);
    const int gBo = (lane >> 3) & 1;
    const uint32_t sAhiB = smem_u32(sAhi), sAloB = smem_u32(sAlo);
    const uint32_t sBhiB = smem_u32(sBhi), sBloB = smem_u32(sBlo);

    float acc[4][4];
#pragma unroll
    for (int n = 0; n < 4; ++n)
#pragma unroll
        for (int j = 0; j < 4; ++j) acc[n][j] = 0.0f;

    uint4 pf[8];
#pragma unroll
    for (int i = 0; i < 8; ++i) { pf[i] = *(const uint4*)srcp[i]; srcp[i] += KC; }

    for (int c = 0; c < CHG; ++c) {
#pragma unroll
        for (int i = 0; i < 8; ++i)
            asm volatile("st.shared.v4.b32 [%0], {%1, %2, %3, %4};"
                         :: "r"(dsta[i]), "r"(pf[i].x), "r"(pf[i].y),
                            "r"(pf[i].z), "r"(pf[i].w) : "memory");
        __syncthreads();

        if (c + 1 < CHG) {
#pragma unroll
            for (int i = 0; i < 8; ++i) { pf[i] = *(const uint4*)srcp[i]; srcp[i] += KC; }
        }

#pragma unroll
        for (int step = 0; step < 4; ++step) {
            const int g0 = step * 2;
            const int gA = g0 + gAo;
            const uint32_t offA = (uint32_t)(mA * 128 + ((gA ^ (mA & 7)) * 16));
            uint32_t ahi[4], alo[4];
            LDSM4(ahi[0], ahi[1], ahi[2], ahi[3], sAhiB + offA);
            LDSM4(alo[0], alo[1], alo[2], alo[3], sAloB + offA);

            uint32_t bhi[4][2], blo[4][2];
#pragma unroll
            for (int ntp = 0; ntp < 2; ++ntp) {
                const int nr = nB + ntp * 16;
                const int gB = g0 + gBo;
                const uint32_t offB = (uint32_t)(nr * 128 + ((gB ^ (nr & 7)) * 16));
                LDSM4(bhi[ntp * 2][0], bhi[ntp * 2][1],
                      bhi[ntp * 2 + 1][0], bhi[ntp * 2 + 1][1], sBhiB + offB);
                LDSM4(blo[ntp * 2][0], blo[ntp * 2][1],
                      blo[ntp * 2 + 1][0], blo[ntp * 2 + 1][1], sBloB + offB);
            }
#pragma unroll
            for (int n = 0; n < 4; ++n) {
                MMA16816(acc[n], ahi, bhi[n]);
                MMA16816(acc[n], ahi, blo[n]);
                MMA16816(acc[n], alo, bhi[n]);
            }
        }
        __syncthreads();
    }

    // partial stores: rows = gate cols, cols = batch
    const int laneg = lane >> 2, lane4 = lane & 3;
    const int row_lo = mtile * 64 + mw * 16 + laneg;
    const int row_hi = row_lo + 8;
#pragma unroll
    for (int n = 0; n < 4; ++n) {
        int col = nw * 32 + n * 8 + lane4 * 2;
        *(float2*)&g_gpartT[ks][row_lo][col] = make_float2(acc[n][0], acc[n][1]);
        *(float2*)&g_gpartT[ks][row_hi][col] = make_float2(acc[n][2], acc[n][3]);
    }
}

// ---------------------------------------------------------------------------
// cell: reduce KSG partials (fixed order), biases, LSTM nonlinearities,
// emit bf16 hi/lo split of h.
// ---------------------------------------------------------------------------
__global__ void cell_kernel(const float* __restrict__ b_ih,
                            const float* __restrict__ b_hh, int t) {
    int idx = blockIdx.x * blockDim.x + threadIdx.x;
    if (idx >= B * HID) return;
    int b = idx & (B - 1), u = idx >> 6;

    float gi = b_ih[u] + b_hh[u];
    float gf = b_ih[HID + u] + b_hh[HID + u];
    float gg = b_ih[2 * HID + u] + b_hh[2 * HID + u];
    float go = b_ih[3 * HID + u] + b_hh[3 * HID + u];
#pragma unroll
    for (int s = 0; s < KSG; ++s) {
        gi += g_gpartT[s][u][b];
        gf += g_gpartT[s][HID + u][b];
        gg += g_gpartT[s][2 * HID + u][b];
        go += g_gpartT[s][3 * HID + u][b];
    }
    float cn = sigm(gf) * g_c[u * B + b] + sigm(gi) * tanhf(gg);
    g_c[u * B + b] = cn;
    float hn = sigm(go) * tanhf(cn);
    __nv_bfloat16 hi = __float2bfloat16(hn);
    g_hhi[b * HID + u] = hi;
    g_hlo[b * HID + u] = __float2bfloat16(hn - __bfloat162float(hi));
}

// ---------------------------------------------------------------------------
// logits via HMMA split-bf16, MT=128, cp.async double-buffered stages.
// 256 threads = 8 warps, 4(M) x 2(N), warp tile m32 x n32.
// ---------------------------------------------------------------------------
__global__ void __launch_bounds__(256, 2)
logits_mma(const float* __restrict__ out_b, int t) {
    extern __shared__ __align__(128) char dsm[];
    __shared__ unsigned long long skeys[4][B];

    const int tid = threadIdx.x, wid = tid >> 5, lane = tid & 31;
    const int mw = wid & 3, nw = wid >> 2;
    const int v0 = blockIdx.x * MT;
    const uint32_t sb0 = smem_u32(dsm);

    // loader: 3072 uint4 per stage, 12 per thread
    const char* srcp[12];
    uint32_t dstrel[12];
#pragma unroll
    for (int i = 0; i < 12; ++i) {
        int s = tid + i * 256;
        int g = s & 7, r;
        uint32_t roff;
        const __nv_bfloat16* base;
        if (s < 1024) {
            r = s >> 3; int v = v0 + r; if (v >= VSZ) v = VSZ - 1;
            base = g_Whi + (size_t)v * HID; roff = 0;
        } else if (s < 2048) {
            r = (s - 1024) >> 3; int v = v0 + r; if (v >= VSZ) v = VSZ - 1;
            base = g_Wlo + (size_t)v * HID; roff = 16384;
        } else if (s < 2560) {
            r = (s - 2048) >> 3; base = g_hhi + r * HID; roff = 32768;
        } else {
            r = (s - 2560) >> 3; base = g_hlo + r * HID; roff = 40960;
        }
        srcp[i] = (const char*)(base + g * 8);
        dstrel[i] = roff + (uint32_t)(r * 128 + ((g ^ (r & 7)) * 16));
    }

    const int mArb = mw * 32 + ((lane >> 3) & 1) * 8 + (lane & 7);
    const int gAo = lane >> 4;
    const int nB = nw * 32 + ((lane >> 4) & 1) * 8 + (lane & 7);
    const int gBo = (lane >> 3) & 1;

    float acc[2][4][4];
#pragma unroll
    for (int mi = 0; mi < 2; ++mi)
#pragma unroll
        for (int n = 0; n < 4; ++n)
#pragma unroll
            for (int j = 0; j < 4; ++j) acc[mi][n][j] = 0.0f;

    // stage 0
#pragma unroll
    for (int i = 0; i < 12; ++i) CPASYNC(sb0 + dstrel[i], srcp[i]);
    CPCOMMIT();
#pragma unroll
    for (int i = 0; i < 12; ++i) srcp[i] += KC * 2;

    for (int c = 0; c < NCHUNK; ++c) {
        const uint32_t sb = sb0 + (uint32_t)(c & 1) * LSTAGE;
        if (c + 1 < NCHUNK) {
            const uint32_t nbuf = sb0 + (uint32_t)((c + 1) & 1) * LSTAGE;
#pragma unroll
            for (int i = 0; i < 12; ++i) CPASYNC(nbuf + dstrel[i], srcp[i]);
            CPCOMMIT();
#pragma unroll
            for (int i = 0; i < 12; ++i) srcp[i] += KC * 2;
            CPWAIT1();
        } else {
            CPWAIT0();
        }
        __syncthreads();

        const uint32_t sWhiB = sb, sWloB = sb + 16384;
        const uint32_t sHhiB = sb + 32768, sHloB = sb + 40960;
#pragma unroll
        for (int step = 0; step < 4; ++step) {
            const int g0 = step * 2;
            const int gA = g0 + gAo, gB = g0 + gBo;
            uint32_t ahi[2][4], alo[2][4];
#pragma unroll
            for (int mi = 0; mi < 2; ++mi) {
                const int row = mArb + mi * 16;
                const uint32_t offA = (uint32_t)(row * 128 + ((gA ^ (row & 7)) * 16));
                LDSM4(ahi[mi][0], ahi[mi][1], ahi[mi][2], ahi[mi][3], sWhiB + offA);
                LDSM4(alo[mi][0], alo[mi][1], alo[mi][2], alo[mi][3], sWloB + offA);
            }
            uint32_t bhi[4][2], blo[4][2];
#pragma unroll
            for (int ntp = 0; ntp < 2; ++ntp) {
                const int nr = nB + ntp * 16;
                const uint32_t offB = (uint32_t)(nr * 128 + ((gB ^ (nr & 7)) * 16));
                LDSM4(bhi[ntp * 2][0], bhi[ntp * 2][1],
                      bhi[ntp * 2 + 1][0], bhi[ntp * 2 + 1][1], sHhiB + offB);
                LDSM4(blo[ntp * 2][0], blo[ntp * 2][1],
                      blo[ntp * 2 + 1][0], blo[ntp * 2 + 1][1], sHloB + offB);
            }
#pragma unroll
            for (int mi = 0; mi < 2; ++mi)
#pragma unroll
                for (int n = 0; n < 4; ++n) {
                    MMA16816(acc[mi][n], ahi[mi], bhi[n]);
                    MMA16816(acc[mi][n], ahi[mi], blo[n]);
                    MMA16816(acc[mi][n], alo[mi], bhi[n]);
                }
        }
        __syncthreads();
    }

    // epilogue: bias + deterministic argmax
    const int laneg = lane >> 2, lane4 = lane & 3;
    float biasL[2], biasH[2];
    bool vL[2], vH[2];
    unsigned int niL[2], niH[2];
#pragma unroll
    for (int mi = 0; mi < 2; ++mi) {
        int ml = v0 + mw * 32 + mi * 16 + laneg, mh = ml + 8;
        vL[mi] = ml < VSZ; vH[mi] = mh < VSZ;
        biasL[mi] = vL[mi] ? out_b[ml] : 0.0f;
        biasH[mi] = vH[mi] ? out_b[mh] : 0.0f;
        niL[mi] = ~(unsigned int)ml; niH[mi] = ~(unsigned int)mh;
    }
#pragma unroll
    for (int n = 0; n < 4; ++n) {
        unsigned long long kA = 0ull, kB = 0ull;
#pragma unroll
        for (int mi = 0; mi < 2; ++mi) {
            if (vL[mi]) {
                unsigned long long k0 = ((unsigned long long)ford(acc[mi][n][0] + biasL[mi]) << 32) | niL[mi];
                unsigned long long k1 = ((unsigned long long)ford(acc[mi][n][1] + biasL[mi]) << 32) | niL[mi];
                if (k0 > kA) kA = k0;
                if (k1 > kB) kB = k1;
            }
            if (vH[mi]) {
                unsigned long long k2 = ((unsigned long long)ford(acc[mi][n][2] + biasH[mi]) << 32) | niH[mi];
                unsigned long long k3 = ((unsigned long long)ford(acc[mi][n][3] + biasH[mi]) << 32) | niH[mi];
                if (k2 > kA) kA = k2;
                if (k3 > kB) kB = k3;
            }
        }
#pragma unroll
        for (int off = 4; off < 32; off <<= 1) {
            unsigned long long oA = __shfl_xor_sync(0xFFFFFFFFu, kA, off);
            unsigned long long oB = __shfl_xor_sync(0xFFFFFFFFu, kB, off);
            if (oA > kA) kA = oA;
            if (oB > kB) kB = oB;
        }
        if (laneg == 0) {
            int ncol = nw * 32 + n * 8 + lane4 * 2;
            skeys[mw][ncol]     = kA;
            skeys[mw][ncol + 1] = kB;
        }
    }
    __syncthreads();
    if (tid < B) {
        unsigned long long k = skeys[0][tid];
        if (skeys[1][tid] > k) k = skeys[1][tid];
        if (skeys[2][tid] > k) k = skeys[2][tid];
        if (skeys[3][tid] > k) k = skeys[3][tid];
        atomicMax(&g_amax[t & 1][tid], k);
    }
}

// ---------------------------------------------------------------------------
__global__ void final_kernel(float* __restrict__ out) {
    int b = threadIdx.x;
    if (b < B) {
        int tok = (int)(~(unsigned int)(g_amax[(TLEN - 1) & 1][b]));
        out[2 * B + b * TLEN + (TLEN - 1)] = (float)tok;
    }
}

// ---------------------------------------------------------------------------
extern "C" void kernel_launch(void* const* d_in, const int* in_sizes, int n_in,
                              void* d_out, int out_size) {
    const float* fused = (const float*)d_in[0];
    const float* emb   = (const float*)d_in[1];
    const float* W_ih  = (const float*)d_in[2];
    const float* W_hh  = (const float*)d_in[3];
    const float* b_ih  = (const float*)d_in[4];
    const float* b_hh  = (const float*)d_in[5];
    const float* out_W = (const float*)d_in[6];
    const float* out_b = (const float*)d_in[7];
    const float* c1_W  = (const float*)d_in[8];
    const float* c1_b  = (const float*)d_in[9];
    const float* c2_W  = (const float*)d_in[10];
    const float* c2_b  = (const float*)d_in[11];
    float* out = (float*)d_out;

    cudaFuncSetAttribute(logits_mma, cudaFuncAttributeMaxDynamicSharedMemorySize,
                         2 * LSTAGE);

    __nv_bfloat16 *pWhi, *pWlo, *pEhi, *pElo, *pIhHi, *pIhLo, *pHhHi, *pHhLo;
    cudaGetSymbolAddress((void**)&pWhi, g_Whi);
    cudaGetSymbolAddress((void**)&pWlo, g_Wlo);
    cudaGetSymbolAddress((void**)&pEhi, g_Ehi);
    cudaGetSymbolAddress((void**)&pElo, g_Elo);
    cudaGetSymbolAddress((void**)&pIhHi, g_WihHi);
    cudaGetSymbolAddress((void**)&pIhLo, g_WihLo);
    cudaGetSymbolAddress((void**)&pHhHi, g_WhhHi);
    cudaGetSymbolAddress((void**)&pHhLo, g_WhhLo);

    init_kernel<<<(B * HID + 255) / 256, 256>>>(fused);
    split_kernel<<<2048, 256>>>(out_W, pWhi, pWlo, (size_t)VSZ * HID);
    split_kernel<<<2048, 256>>>(emb, pEhi, pElo, (size_t)VSZ * HID);
    split_kernel<<<512, 256>>>(W_ih, pIhHi, pIhLo, (size_t)4 * HID * HID);
    split_kernel<<<512, 256>>>(W_hh, pHhHi, pHhLo, (size_t)4 * HID * HID);
    closed1_kernel<<<C1, 64>>>(fused, c1_W, c1_b);
    closed2_kernel<<<32, 128>>>(c2_W, c2_b, out);

    dim3 ggrid(4 * HID / 64, KSG);   // (48, 4)
    for (int t = 0; t < TLEN; ++t) {
        gates_mma<<<ggrid, 256>>>(t, out);
        cell_kernel<<<(B * HID + 255) / 256, 256>>>(b_ih, b_hh, t);
        logits_mma<<<GRID_L, 256, 2 * LSTAGE>>>(out_b, t);
    }
    final_kernel<<<1, 64>>>(out);
}